// round 1
// baseline (speedup 1.0000x reference)
#include <cuda_runtime.h>
#include <cuda_bf16.h>
#include <math.h>

#define NN 100000
#define EE 1600000
#define GG 32
#define INC 100
#define HC 64
#define EPS 1e-5f

// ---------------- scratch (no allocation allowed) ----------------
__device__ float g_deg [NN];
__device__ float g_dinv[NN];
__device__ float g_norm[EE];
__device__ float g_bufA[(size_t)NN * HC];
__device__ float g_bufB[(size_t)NN * HC];
__device__ float g_pool[GG * HC];
__device__ float g_cnt [GG];

// ---------------- small utility kernels ----------------
__global__ void zero_f4_kernel(float* p, int n_float4) {
    int i = blockIdx.x * blockDim.x + threadIdx.x;
    if (i < n_float4) ((float4*)p)[i] = make_float4(0.f, 0.f, 0.f, 0.f);
}

__global__ void init_deg_kernel() {
    int i = blockIdx.x * blockDim.x + threadIdx.x;
    if (i < NN) g_deg[i] = 1.0f;   // self-loop weight
}

__global__ void deg_accum_kernel(const int* __restrict__ dst,
                                 const float* __restrict__ ew) {
    int e = blockIdx.x * blockDim.x + threadIdx.x;
    if (e < EE) atomicAdd(&g_deg[dst[e]], fabsf(ew[e]));
}

__global__ void dinv_kernel() {
    int i = blockIdx.x * blockDim.x + threadIdx.x;
    if (i < NN) g_dinv[i] = rsqrtf(g_deg[i]);   // deg >= 1 always (self loop)
}

__global__ void norm_kernel(const int* __restrict__ src,
                            const int* __restrict__ dst,
                            const float* __restrict__ ew) {
    int e = blockIdx.x * blockDim.x + threadIdx.x;
    if (e < EE) g_norm[e] = g_dinv[src[e]] * fabsf(ew[e]) * g_dinv[dst[e]];
}

// ---------------- GEMM: Y[N,64] = X[N,DIN] @ W[DIN,64] ----------------
// block: (64,4) threads, 32 nodes per block. W resident in smem.
template <int DIN>
__global__ void gemm_kernel(const float* __restrict__ X,
                            const float* __restrict__ W,
                            float* __restrict__ Y) {
    __shared__ float Ws[DIN * 64];
    __shared__ float Xs[32 * DIN];
    const int tx  = threadIdx.x;          // 0..63  (output channel)
    const int ty  = threadIdx.y;          // 0..3
    const int tid = ty * 64 + tx;
    const int base = blockIdx.x * 32;

    for (int i = tid; i < DIN * 64; i += 256) Ws[i] = W[i];
    for (int i = tid; i < 32 * DIN; i += 256) {
        int n = i / DIN, k = i - n * DIN;
        Xs[i] = X[(size_t)(base + n) * DIN + k];
    }
    __syncthreads();

    #pragma unroll
    for (int chunk = 0; chunk < 2; chunk++) {
        const int n0 = ty * 8 + chunk * 4;
        float a0 = 0.f, a1 = 0.f, a2 = 0.f, a3 = 0.f;
        const float* x0 = &Xs[(n0 + 0) * DIN];
        const float* x1 = &Xs[(n0 + 1) * DIN];
        const float* x2 = &Xs[(n0 + 2) * DIN];
        const float* x3 = &Xs[(n0 + 3) * DIN];
        #pragma unroll 4
        for (int k = 0; k < DIN; k++) {
            float wv = Ws[k * 64 + tx];
            a0 = fmaf(x0[k], wv, a0);
            a1 = fmaf(x1[k], wv, a1);
            a2 = fmaf(x2[k], wv, a2);
            a3 = fmaf(x3[k], wv, a3);
        }
        Y[(size_t)(base + n0 + 0) * 64 + tx] = a0;
        Y[(size_t)(base + n0 + 1) * 64 + tx] = a1;
        Y[(size_t)(base + n0 + 2) * 64 + tx] = a2;
        Y[(size_t)(base + n0 + 3) * 64 + tx] = a3;
    }
}

// ---------------- propagation: out[dst] += H[src] * norm ----------------
// 16 threads per edge, float4 per thread (64 channels).
__global__ void prop_kernel(const float* __restrict__ H,
                            const int* __restrict__ src,
                            const int* __restrict__ dst,
                            float* __restrict__ out) {
    long long idx = (long long)blockIdx.x * blockDim.x + threadIdx.x;
    const long long total = (long long)EE * 16;
    if (idx >= total) return;
    int e  = (int)(idx >> 4);
    int c  = (int)(idx & 15) << 2;
    int s  = src[e];
    int d  = dst[e];
    float nv = g_norm[e];
    float4 v = *(const float4*)(H + (size_t)s * 64 + c);
    float4 r = make_float4(v.x * nv, v.y * nv, v.z * nv, v.w * nv);
    atomicAdd((float4*)(out + (size_t)d * 64 + c), r);
}

// ---------------- epilogue: self-loop + bias + BN + ReLU ----------------
__global__ void epi_kernel(const float* __restrict__ selfh,   // GEMM output
                           const float* __restrict__ agg,     // neighbor agg
                           const float* __restrict__ b,
                           const float* __restrict__ g,
                           const float* __restrict__ bt,
                           const float* __restrict__ rm,
                           const float* __restrict__ rv,
                           float* __restrict__ out) {
    int idx = blockIdx.x * blockDim.x + threadIdx.x;
    if (idx >= NN * HC) return;
    int i = idx >> 6;
    int c = idx & 63;
    float dv = g_dinv[i];
    float val = agg[idx] + selfh[idx] * dv * dv + b[c];
    float scale = g[c] * rsqrtf(rv[c] + EPS);
    val = (val - rm[c]) * scale + bt[c];
    out[idx] = fmaxf(val, 0.f);
}

// ---------------- pooling ----------------
__global__ void pool_kernel(const float* __restrict__ H,
                            const int* __restrict__ batch) {
    long long idx = (long long)blockIdx.x * blockDim.x + threadIdx.x;
    const long long total = (long long)NN * 16;
    if (idx >= total) return;
    int i  = (int)(idx >> 4);
    int c  = (int)(idx & 15) << 2;
    int gr = batch[i];
    float4 v = *(const float4*)(H + (size_t)i * 64 + c);
    atomicAdd((float4*)(g_pool + gr * 64 + c), v);
    if (c == 0) atomicAdd(&g_cnt[gr], 1.0f);
}

__global__ void out_kernel(float* __restrict__ out) {
    int gr = blockIdx.x;        // 0..31
    int c  = threadIdx.x;       // 0..127
    float s = g_pool[gr * 64 + (c & 63)];
    float cc = fmaxf(g_cnt[gr], 1.0f);
    out[gr * 128 + c] = (c < 64) ? s / cc : s;
}

// ---------------- launch ----------------
extern "C" void kernel_launch(void* const* d_in, const int* in_sizes, int n_in,
                              void* d_out, int out_size) {
    const float* x     = (const float*)d_in[0];
    const int*   ei    = (const int*)  d_in[1];
    const float* ew    = (const float*)d_in[2];
    const int*   batch = (const int*)  d_in[3];
    const int*   src   = ei;
    const int*   dst   = ei + EE;
    float* out = (float*)d_out;

    const float* Wl[3], *bl[3], *gl[3], *btl[3], *rml[3], *rvl[3];
    for (int l = 0; l < 3; l++) {
        Wl[l]  = (const float*)d_in[4 + 6 * l + 0];
        bl[l]  = (const float*)d_in[4 + 6 * l + 1];
        gl[l]  = (const float*)d_in[4 + 6 * l + 2];
        btl[l] = (const float*)d_in[4 + 6 * l + 3];
        rml[l] = (const float*)d_in[4 + 6 * l + 4];
        rvl[l] = (const float*)d_in[4 + 6 * l + 5];
    }

    float *bufA, *bufB, *pool_p, *cnt_p;
    cudaGetSymbolAddress((void**)&bufA,   g_bufA);
    cudaGetSymbolAddress((void**)&bufB,   g_bufB);
    cudaGetSymbolAddress((void**)&pool_p, g_pool);
    cudaGetSymbolAddress((void**)&cnt_p,  g_cnt);

    const int T = 256;

    // normalization constants
    init_deg_kernel<<<(NN + T - 1) / T, T>>>();
    deg_accum_kernel<<<(EE + T - 1) / T, T>>>(dst, ew);
    dinv_kernel<<<(NN + T - 1) / T, T>>>();
    norm_kernel<<<(EE + T - 1) / T, T>>>(src, dst, ew);

    dim3 gemmBlock(64, 4);
    const int gemmGrid = NN / 32;                       // 3125 (N % 32 == 0)
    const int propGrid = (int)(((long long)EE * 16 + T - 1) / T);
    const int epiGrid  = (NN * HC + T - 1) / T;
    const int zeroGrid = (NN * HC / 4 + T - 1) / T;

    // ---- layer 0: x -> bufB ----
    gemm_kernel<INC><<<gemmGrid, gemmBlock>>>(x, Wl[0], bufA);
    zero_f4_kernel<<<zeroGrid, T>>>(bufB, NN * HC / 4);
    prop_kernel<<<propGrid, T>>>(bufA, src, dst, bufB);
    epi_kernel<<<epiGrid, T>>>(bufA, bufB, bl[0], gl[0], btl[0], rml[0], rvl[0], bufB);

    // ---- layers 1,2: bufB -> bufB (via bufA) ----
    for (int l = 1; l < 3; l++) {
        gemm_kernel<HC><<<gemmGrid, gemmBlock>>>(bufB, Wl[l], bufA);
        zero_f4_kernel<<<zeroGrid, T>>>(bufB, NN * HC / 4);
        prop_kernel<<<propGrid, T>>>(bufA, src, dst, bufB);
        epi_kernel<<<epiGrid, T>>>(bufA, bufB, bl[l], gl[l], btl[l], rml[l], rvl[l], bufB);
    }

    // ---- pooling ----
    zero_f4_kernel<<<((GG * HC + GG) / 4 + T - 1) / T, T>>>(pool_p, GG * HC / 4);
    zero_f4_kernel<<<1, T>>>(cnt_p, GG / 4);
    pool_kernel<<<(int)(((long long)NN * 16 + T - 1) / T), T>>>(bufB, batch);
    out_kernel<<<GG, 128>>>(out);
}

// round 2
// speedup vs baseline: 1.2578x; 1.2578x over previous
#include <cuda_runtime.h>
#include <cuda_bf16.h>
#include <math.h>

#define NN 100000
#define EE 1600000
#define GG 32
#define INC 100
#define HC 64
#define EPS 1e-5f
#define NBLK 98            // ceil(NN/1024)

// ---------------- scratch ----------------
__device__ float g_deg  [NN];
__device__ float g_dinv [NN];
__device__ int   g_cnt_e[NN];         // per-node incoming edge count
__device__ int   g_rowst[NN];         // CSR row start
__device__ int   g_cur  [NN];         // scatter cursor; after scatter = row end
__device__ int   g_bsum [128];
__device__ int   g_srcs [EE];         // CSR: src per slot
__device__ float g_wn   [EE];         // CSR: norm per slot
__device__ float g_bufA [(size_t)NN * HC];
__device__ float g_bufB [(size_t)NN * HC];
__device__ float g_pool [GG * HC];
__device__ float g_gcnt [GG];

// ---------------- init / degree ----------------
__global__ void init_kernel() {
    int i = blockIdx.x * blockDim.x + threadIdx.x;
    if (i < NN) { g_deg[i] = 1.0f; g_cnt_e[i] = 0; }
    if (i < GG * HC) g_pool[i] = 0.f;
    if (i < GG) g_gcnt[i] = 0.f;
}

__global__ void edge_accum_kernel(const int* __restrict__ dst,
                                  const float* __restrict__ ew) {
    int e = blockIdx.x * blockDim.x + threadIdx.x;
    if (e >= EE) return;
    int d = dst[e];
    atomicAdd(&g_deg[d], fabsf(ew[e]));
    atomicAdd(&g_cnt_e[d], 1);
}

__global__ void dinv_kernel() {
    int i = blockIdx.x * blockDim.x + threadIdx.x;
    if (i < NN) g_dinv[i] = rsqrtf(g_deg[i]);  // deg >= 1 (self-loop)
}

// ---------------- 2-level exclusive scan of g_cnt_e -> g_rowst ----------------
__global__ void scan_block_kernel() {
    __shared__ int sh[1024];
    int tid = threadIdx.x;
    int i = blockIdx.x * 1024 + tid;
    int v = (i < NN) ? g_cnt_e[i] : 0;
    sh[tid] = v;
    __syncthreads();
    #pragma unroll
    for (int off = 1; off < 1024; off <<= 1) {
        int t = (tid >= off) ? sh[tid - off] : 0;
        __syncthreads();
        sh[tid] += t;
        __syncthreads();
    }
    if (i < NN) g_rowst[i] = sh[tid] - v;          // exclusive within block
    if (tid == 1023) g_bsum[blockIdx.x] = sh[1023];
}

__global__ void scan_bsum_kernel() {
    __shared__ int sh[128];
    int tid = threadIdx.x;
    int v = (tid < NBLK) ? g_bsum[tid] : 0;
    sh[tid] = v;
    __syncthreads();
    #pragma unroll
    for (int off = 1; off < 128; off <<= 1) {
        int t = (tid >= off) ? sh[tid - off] : 0;
        __syncthreads();
        sh[tid] += t;
        __syncthreads();
    }
    if (tid < NBLK) g_bsum[tid] = sh[tid] - v;     // exclusive block offsets
}

__global__ void add_offsets_kernel() {
    int i = blockIdx.x * blockDim.x + threadIdx.x;
    if (i >= NN) return;
    int r = g_rowst[i] + g_bsum[i >> 10];
    g_rowst[i] = r;
    g_cur[i] = r;
}

// ---------------- scatter edges into CSR ----------------
__global__ void scatter_kernel(const int* __restrict__ src,
                               const int* __restrict__ dst,
                               const float* __restrict__ ew) {
    int e = blockIdx.x * blockDim.x + threadIdx.x;
    if (e >= EE) return;
    int s = src[e], d = dst[e];
    int pos = atomicAdd(&g_cur[d], 1);
    g_srcs[pos] = s;
    g_wn[pos]   = g_dinv[s] * fabsf(ew[e]) * g_dinv[d];
}

// ---------------- GEMM: Y[N,64] = X[N,DIN] @ W[DIN,64] ----------------
template <int DIN>
__global__ void gemm_kernel(const float* __restrict__ X,
                            const float* __restrict__ W,
                            float* __restrict__ Y) {
    __shared__ float Ws[DIN * 64];
    __shared__ float Xs[32 * DIN];
    const int tx  = threadIdx.x;
    const int ty  = threadIdx.y;
    const int tid = ty * 64 + tx;
    const int base = blockIdx.x * 32;

    for (int i = tid; i < DIN * 64; i += 256) Ws[i] = W[i];
    for (int i = tid; i < 32 * DIN; i += 256) {
        int n = i / DIN, k = i - n * DIN;
        Xs[i] = X[(size_t)(base + n) * DIN + k];
    }
    __syncthreads();

    #pragma unroll
    for (int chunk = 0; chunk < 2; chunk++) {
        const int n0 = ty * 8 + chunk * 4;
        float a0 = 0.f, a1 = 0.f, a2 = 0.f, a3 = 0.f;
        const float* x0 = &Xs[(n0 + 0) * DIN];
        const float* x1 = &Xs[(n0 + 1) * DIN];
        const float* x2 = &Xs[(n0 + 2) * DIN];
        const float* x3 = &Xs[(n0 + 3) * DIN];
        #pragma unroll 4
        for (int k = 0; k < DIN; k++) {
            float wv = Ws[k * 64 + tx];
            a0 = fmaf(x0[k], wv, a0);
            a1 = fmaf(x1[k], wv, a1);
            a2 = fmaf(x2[k], wv, a2);
            a3 = fmaf(x3[k], wv, a3);
        }
        Y[(size_t)(base + n0 + 0) * 64 + tx] = a0;
        Y[(size_t)(base + n0 + 1) * 64 + tx] = a1;
        Y[(size_t)(base + n0 + 2) * 64 + tx] = a2;
        Y[(size_t)(base + n0 + 3) * 64 + tx] = a3;
    }
}

// ---------------- fused CSR gather-reduce + BN + ReLU (+ pooling) ----------------
// one warp per dst node; lane owns channels {2*lane, 2*lane+1}
template <bool LAST>
__global__ void prop_fused_kernel(const float* __restrict__ H,
                                  const float* __restrict__ b,
                                  const float* __restrict__ g,
                                  const float* __restrict__ bt,
                                  const float* __restrict__ rm,
                                  const float* __restrict__ rv,
                                  const int* __restrict__ batch,
                                  float* __restrict__ out) {
    const int node = blockIdx.x * (blockDim.x >> 5) + (threadIdx.x >> 5);
    if (node >= NN) return;
    const int lane = threadIdx.x & 31;
    const int ch   = lane << 1;

    const int s0 = g_rowst[node];
    const int s1 = g_cur[node];   // row end after scatter

    float ax0 = 0.f, ay0 = 0.f, ax1 = 0.f, ay1 = 0.f;
    float ax2 = 0.f, ay2 = 0.f, ax3 = 0.f, ay3 = 0.f;

    for (int j = s0; j < s1; j += 32) {
        const int m = min(32, s1 - j);
        int   sv = 0; float wv = 0.f;
        if (lane < m) { sv = g_srcs[j + lane]; wv = g_wn[j + lane]; }
        int k = 0;
        for (; k + 4 <= m; k += 4) {
            int   sA = __shfl_sync(0xffffffffu, sv, k);
            float wA = __shfl_sync(0xffffffffu, wv, k);
            int   sB = __shfl_sync(0xffffffffu, sv, k + 1);
            float wB = __shfl_sync(0xffffffffu, wv, k + 1);
            int   sC = __shfl_sync(0xffffffffu, sv, k + 2);
            float wC = __shfl_sync(0xffffffffu, wv, k + 2);
            int   sD = __shfl_sync(0xffffffffu, sv, k + 3);
            float wD = __shfl_sync(0xffffffffu, wv, k + 3);
            float2 vA = *(const float2*)(H + (size_t)sA * 64 + ch);
            float2 vB = *(const float2*)(H + (size_t)sB * 64 + ch);
            float2 vC = *(const float2*)(H + (size_t)sC * 64 + ch);
            float2 vD = *(const float2*)(H + (size_t)sD * 64 + ch);
            ax0 = fmaf(wA, vA.x, ax0); ay0 = fmaf(wA, vA.y, ay0);
            ax1 = fmaf(wB, vB.x, ax1); ay1 = fmaf(wB, vB.y, ay1);
            ax2 = fmaf(wC, vC.x, ax2); ay2 = fmaf(wC, vC.y, ay2);
            ax3 = fmaf(wD, vD.x, ax3); ay3 = fmaf(wD, vD.y, ay3);
        }
        for (; k < m; k++) {
            int   sA = __shfl_sync(0xffffffffu, sv, k);
            float wA = __shfl_sync(0xffffffffu, wv, k);
            float2 vA = *(const float2*)(H + (size_t)sA * 64 + ch);
            ax0 = fmaf(wA, vA.x, ax0); ay0 = fmaf(wA, vA.y, ay0);
        }
    }

    // self-loop + bias + BN + ReLU
    const float dv = g_dinv[node];
    const float dv2 = dv * dv;
    float2 hv = *(const float2*)(H + (size_t)node * 64 + ch);
    float sx = (ax0 + ax1) + (ax2 + ax3) + hv.x * dv2 + b[ch];
    float sy = (ay0 + ay1) + (ay2 + ay3) + hv.y * dv2 + b[ch + 1];
    float scx = g[ch]     * rsqrtf(rv[ch]     + EPS);
    float scy = g[ch + 1] * rsqrtf(rv[ch + 1] + EPS);
    sx = fmaxf((sx - rm[ch])     * scx + bt[ch],     0.f);
    sy = fmaxf((sy - rm[ch + 1]) * scy + bt[ch + 1], 0.f);
    float2 r = make_float2(sx, sy);
    *(float2*)(out + (size_t)node * 64 + ch) = r;

    if (LAST) {
        int gr = batch[node];
        atomicAdd((float2*)(g_pool + gr * 64 + ch), r);
        if (lane == 0) atomicAdd(&g_gcnt[gr], 1.0f);
    }
}

// ---------------- final output ----------------
__global__ void out_kernel(float* __restrict__ out) {
    int gr = blockIdx.x;
    int c  = threadIdx.x;
    float s  = g_pool[gr * 64 + (c & 63)];
    float cc = fmaxf(g_gcnt[gr], 1.0f);
    out[gr * 128 + c] = (c < 64) ? s / cc : s;
}

// ---------------- launch ----------------
extern "C" void kernel_launch(void* const* d_in, const int* in_sizes, int n_in,
                              void* d_out, int out_size) {
    const float* x     = (const float*)d_in[0];
    const int*   ei    = (const int*)  d_in[1];
    const float* ew    = (const float*)d_in[2];
    const int*   batch = (const int*)  d_in[3];
    const int*   src   = ei;
    const int*   dst   = ei + EE;
    float* out = (float*)d_out;

    const float *Wl[3], *bl[3], *gl[3], *btl[3], *rml[3], *rvl[3];
    for (int l = 0; l < 3; l++) {
        Wl[l]  = (const float*)d_in[4 + 6 * l + 0];
        bl[l]  = (const float*)d_in[4 + 6 * l + 1];
        gl[l]  = (const float*)d_in[4 + 6 * l + 2];
        btl[l] = (const float*)d_in[4 + 6 * l + 3];
        rml[l] = (const float*)d_in[4 + 6 * l + 4];
        rvl[l] = (const float*)d_in[4 + 6 * l + 5];
    }

    float *bufA, *bufB;
    cudaGetSymbolAddress((void**)&bufA, g_bufA);
    cudaGetSymbolAddress((void**)&bufB, g_bufB);

    const int T = 256;
    const int nGrid = (NN + T - 1) / T;
    const int eGrid = (EE + T - 1) / T;

    // ---- CSR build (once; reused by all 3 layers) ----
    init_kernel<<<nGrid, T>>>();
    edge_accum_kernel<<<eGrid, T>>>(dst, ew);
    dinv_kernel<<<nGrid, T>>>();
    scan_block_kernel<<<NBLK, 1024>>>();
    scan_bsum_kernel<<<1, 128>>>();
    add_offsets_kernel<<<nGrid, T>>>();
    scatter_kernel<<<eGrid, T>>>(src, dst, ew);

    dim3 gemmBlock(64, 4);
    const int gemmGrid = NN / 32;
    const int propGrid = (NN + 7) / 8;     // 8 warps/block, warp per node

    // ---- layer 0 ----
    gemm_kernel<INC><<<gemmGrid, gemmBlock>>>(x, Wl[0], bufA);
    prop_fused_kernel<false><<<propGrid, 256>>>(bufA, bl[0], gl[0], btl[0],
                                                rml[0], rvl[0], batch, bufB);
    // ---- layer 1 ----
    gemm_kernel<HC><<<gemmGrid, gemmBlock>>>(bufB, Wl[1], bufA);
    prop_fused_kernel<false><<<propGrid, 256>>>(bufA, bl[1], gl[1], btl[1],
                                                rml[1], rvl[1], batch, bufB);
    // ---- layer 2 (fused pooling) ----
    gemm_kernel<HC><<<gemmGrid, gemmBlock>>>(bufB, Wl[2], bufA);
    prop_fused_kernel<true><<<propGrid, 256>>>(bufA, bl[2], gl[2], btl[2],
                                               rml[2], rvl[2], batch, bufB);

    out_kernel<<<GG, 128>>>(out);
}

// round 3
// speedup vs baseline: 1.6037x; 1.2750x over previous
#include <cuda_runtime.h>
#include <cuda_bf16.h>
#include <math.h>

#define NN 100000
#define EE 1600000
#define GG 32
#define INC 100
#define HC 64
#define EPS 1e-5f
#define NBLK 98            // ceil(NN/1024)

// ---------------- scratch ----------------
__device__ float g_deg  [NN];
__device__ float g_dinv [NN];
__device__ int   g_cnt_e[NN];         // per-node incoming edge count
__device__ int   g_rowst[NN];         // CSR row start
__device__ int   g_bsum [128];
__device__ int   g_pos  [EE];         // per-edge slot within its dst row
__device__ int   g_srcs [EE];         // CSR: src per slot
__device__ float g_wn   [EE];         // CSR: norm per slot
__device__ float g_bufA [(size_t)NN * HC];
__device__ float g_bufB [(size_t)NN * HC];
__device__ float g_pool [GG * HC];
__device__ float g_gcnt [GG];

// ---------------- init / degree ----------------
__global__ void init_kernel() {
    int i = blockIdx.x * blockDim.x + threadIdx.x;
    if (i < NN) { g_deg[i] = 1.0f; g_cnt_e[i] = 0; }
    if (i < GG * HC) g_pool[i] = 0.f;
    if (i < GG) g_gcnt[i] = 0.f;
}

__global__ void edge_accum_kernel(const int* __restrict__ dst,
                                  const float* __restrict__ ew) {
    int e = blockIdx.x * blockDim.x + threadIdx.x;
    if (e >= EE) return;
    int d = dst[e];
    atomicAdd(&g_deg[d], fabsf(ew[e]));
    g_pos[e] = atomicAdd(&g_cnt_e[d], 1);   // reserve slot now, reuse later
}

// ---------------- 2-level exclusive scan of g_cnt_e -> g_rowst ----------------
__global__ void scan_block_kernel() {
    __shared__ int sh[1024];
    int tid = threadIdx.x;
    int i = blockIdx.x * 1024 + tid;
    int v = (i < NN) ? g_cnt_e[i] : 0;
    sh[tid] = v;
    __syncthreads();
    #pragma unroll
    for (int off = 1; off < 1024; off <<= 1) {
        int t = (tid >= off) ? sh[tid - off] : 0;
        __syncthreads();
        sh[tid] += t;
        __syncthreads();
    }
    if (i < NN) g_rowst[i] = sh[tid] - v;
    if (tid == 1023) g_bsum[blockIdx.x] = sh[1023];
}

__global__ void scan_bsum_kernel() {
    __shared__ int sh[128];
    int tid = threadIdx.x;
    int v = (tid < NBLK) ? g_bsum[tid] : 0;
    sh[tid] = v;
    __syncthreads();
    #pragma unroll
    for (int off = 1; off < 128; off <<= 1) {
        int t = (tid >= off) ? sh[tid - off] : 0;
        __syncthreads();
        sh[tid] += t;
        __syncthreads();
    }
    if (tid < NBLK) g_bsum[tid] = sh[tid] - v;
}

__global__ void add_offsets_kernel() {
    int i = blockIdx.x * blockDim.x + threadIdx.x;
    if (i >= NN) return;
    g_rowst[i] += g_bsum[i >> 10];
    g_dinv[i] = rsqrtf(g_deg[i]);           // deg >= 1 (self-loop)
}

// ---------------- scatter edges into CSR (no atomics) ----------------
__global__ void scatter_kernel(const int* __restrict__ src,
                               const int* __restrict__ dst,
                               const float* __restrict__ ew) {
    int e = blockIdx.x * blockDim.x + threadIdx.x;
    if (e >= EE) return;
    int s = src[e], d = dst[e];
    int pos = g_rowst[d] + g_pos[e];
    g_srcs[pos] = s;
    g_wn[pos]   = g_dinv[s] * fabsf(ew[e]) * g_dinv[d];
}

// ---------------- GEMM: Y[N,64] = X[N,DIN] @ W[DIN,64] ----------------
// 64x64 tile, 256 threads, 4x4 micro-tile, K-chunks of 32, X transposed in smem.
template <int DIN>
__global__ void __launch_bounds__(256) gemm_kernel(const float* __restrict__ X,
                                                   const float* __restrict__ W,
                                                   float* __restrict__ Y) {
    __shared__ float Xs[32 * 68];   // [kk][n], padded
    __shared__ float Ws[32 * 64];   // [kk][c]
    const int t  = threadIdx.x;
    const int tx = t & 15;          // channel group (4 ch)
    const int ty = t >> 4;          // node group (4 nodes)
    const int base = blockIdx.x * 64;

    float4 acc0 = {0,0,0,0}, acc1 = {0,0,0,0}, acc2 = {0,0,0,0}, acc3 = {0,0,0,0};

    for (int k0 = 0; k0 < DIN; k0 += 32) {
        const int kc = (DIN - k0 < 32) ? (DIN - k0) : 32;
        // load X tile (64 nodes x up-to-32 k), transpose into Xs[kk][n]
        #pragma unroll
        for (int i = t; i < 512; i += 256) {
            int n  = i >> 3;
            int kq = (i & 7) << 2;
            float4 v = {0.f, 0.f, 0.f, 0.f};
            int nn = base + n;
            if (nn < NN && kq < kc)
                v = *(const float4*)(X + (size_t)nn * DIN + k0 + kq);
            Xs[(kq + 0) * 68 + n] = v.x;
            Xs[(kq + 1) * 68 + n] = v.y;
            Xs[(kq + 2) * 68 + n] = v.z;
            Xs[(kq + 3) * 68 + n] = v.w;
        }
        // load W tile (up-to-32 k x 64 ch)
        #pragma unroll
        for (int i = t; i < 512; i += 256) {
            int kk = i >> 4;
            int cq = (i & 15) << 2;
            float4 w = {0.f, 0.f, 0.f, 0.f};
            if (kk < kc)
                w = *(const float4*)(W + (size_t)(k0 + kk) * 64 + cq);
            *(float4*)&Ws[kk * 64 + cq] = w;
        }
        __syncthreads();

        for (int kk = 0; kk < kc; kk++) {
            float4 a = *(const float4*)&Xs[kk * 68 + (ty << 2)];
            float4 b = *(const float4*)&Ws[kk * 64 + (tx << 2)];
            acc0.x = fmaf(a.x, b.x, acc0.x); acc0.y = fmaf(a.x, b.y, acc0.y);
            acc0.z = fmaf(a.x, b.z, acc0.z); acc0.w = fmaf(a.x, b.w, acc0.w);
            acc1.x = fmaf(a.y, b.x, acc1.x); acc1.y = fmaf(a.y, b.y, acc1.y);
            acc1.z = fmaf(a.y, b.z, acc1.z); acc1.w = fmaf(a.y, b.w, acc1.w);
            acc2.x = fmaf(a.z, b.x, acc2.x); acc2.y = fmaf(a.z, b.y, acc2.y);
            acc2.z = fmaf(a.z, b.z, acc2.z); acc2.w = fmaf(a.z, b.w, acc2.w);
            acc3.x = fmaf(a.w, b.x, acc3.x); acc3.y = fmaf(a.w, b.y, acc3.y);
            acc3.z = fmaf(a.w, b.z, acc3.z); acc3.w = fmaf(a.w, b.w, acc3.w);
        }
        __syncthreads();
    }

    const int n0 = base + (ty << 2);
    const int c0 = tx << 2;
    if (n0 + 0 < NN) *(float4*)(Y + (size_t)(n0 + 0) * 64 + c0) = acc0;
    if (n0 + 1 < NN) *(float4*)(Y + (size_t)(n0 + 1) * 64 + c0) = acc1;
    if (n0 + 2 < NN) *(float4*)(Y + (size_t)(n0 + 2) * 64 + c0) = acc2;
    if (n0 + 3 < NN) *(float4*)(Y + (size_t)(n0 + 3) * 64 + c0) = acc3;
}

// ---------------- fused CSR gather-reduce + BN + ReLU (+ pooling) ----------------
// half-warp (16 lanes) per dst node; lane owns 4 channels (float4)
template <bool LAST>
__global__ void prop_fused_kernel(const float* __restrict__ H,
                                  const float* __restrict__ b,
                                  const float* __restrict__ g,
                                  const float* __restrict__ bt,
                                  const float* __restrict__ rm,
                                  const float* __restrict__ rv,
                                  const int* __restrict__ batch,
                                  float* __restrict__ out) {
    const int warp  = blockIdx.x * (blockDim.x >> 5) + (threadIdx.x >> 5);
    const int lane  = threadIdx.x & 31;
    const int half  = lane >> 4;
    const int sub   = lane & 15;
    const int node  = (warp << 1) + half;
    if (node >= NN) return;
    const int ch = sub << 2;
    const unsigned hmask = half ? 0xffff0000u : 0x0000ffffu;

    const int s0 = g_rowst[node];
    const int s1 = s0 + g_cnt_e[node];

    float4 a0 = {0,0,0,0}, a1 = {0,0,0,0}, a2 = {0,0,0,0}, a3 = {0,0,0,0};

    for (int j = s0; j < s1; j += 16) {
        const int m = min(16, s1 - j);
        int sv = 0; float wv = 0.f;
        if (sub < m) { sv = g_srcs[j + sub]; wv = g_wn[j + sub]; }
        int k = 0;
        for (; k + 4 <= m; k += 4) {
            int   sA = __shfl_sync(hmask, sv, k,     16);
            float wA = __shfl_sync(hmask, wv, k,     16);
            int   sB = __shfl_sync(hmask, sv, k + 1, 16);
            float wB = __shfl_sync(hmask, wv, k + 1, 16);
            int   sC = __shfl_sync(hmask, sv, k + 2, 16);
            float wC = __shfl_sync(hmask, wv, k + 2, 16);
            int   sD = __shfl_sync(hmask, sv, k + 3, 16);
            float wD = __shfl_sync(hmask, wv, k + 3, 16);
            float4 vA = *(const float4*)(H + (size_t)sA * 64 + ch);
            float4 vB = *(const float4*)(H + (size_t)sB * 64 + ch);
            float4 vC = *(const float4*)(H + (size_t)sC * 64 + ch);
            float4 vD = *(const float4*)(H + (size_t)sD * 64 + ch);
            a0.x = fmaf(wA, vA.x, a0.x); a0.y = fmaf(wA, vA.y, a0.y);
            a0.z = fmaf(wA, vA.z, a0.z); a0.w = fmaf(wA, vA.w, a0.w);
            a1.x = fmaf(wB, vB.x, a1.x); a1.y = fmaf(wB, vB.y, a1.y);
            a1.z = fmaf(wB, vB.z, a1.z); a1.w = fmaf(wB, vB.w, a1.w);
            a2.x = fmaf(wC, vC.x, a2.x); a2.y = fmaf(wC, vC.y, a2.y);
            a2.z = fmaf(wC, vC.z, a2.z); a2.w = fmaf(wC, vC.w, a2.w);
            a3.x = fmaf(wD, vD.x, a3.x); a3.y = fmaf(wD, vD.y, a3.y);
            a3.z = fmaf(wD, vD.z, a3.z); a3.w = fmaf(wD, vD.w, a3.w);
        }
        for (; k < m; k++) {
            int   sA = __shfl_sync(hmask, sv, k, 16);
            float wA = __shfl_sync(hmask, wv, k, 16);
            float4 vA = *(const float4*)(H + (size_t)sA * 64 + ch);
            a0.x = fmaf(wA, vA.x, a0.x); a0.y = fmaf(wA, vA.y, a0.y);
            a0.z = fmaf(wA, vA.z, a0.z); a0.w = fmaf(wA, vA.w, a0.w);
        }
    }

    // combine + self-loop + bias + BN + ReLU
    const float dv  = g_dinv[node];
    const float dv2 = dv * dv;
    float4 hv  = *(const float4*)(H + (size_t)node * 64 + ch);
    float4 bb  = *(const float4*)(b  + ch);
    float4 gg  = *(const float4*)(g  + ch);
    float4 btv = *(const float4*)(bt + ch);
    float4 rmv = *(const float4*)(rm + ch);
    float4 rvv = *(const float4*)(rv + ch);

    float sx = (a0.x + a1.x) + (a2.x + a3.x) + hv.x * dv2 + bb.x;
    float sy = (a0.y + a1.y) + (a2.y + a3.y) + hv.y * dv2 + bb.y;
    float sz = (a0.z + a1.z) + (a2.z + a3.z) + hv.z * dv2 + bb.z;
    float sw = (a0.w + a1.w) + (a2.w + a3.w) + hv.w * dv2 + bb.w;

    sx = fmaxf((sx - rmv.x) * (gg.x * rsqrtf(rvv.x + EPS)) + btv.x, 0.f);
    sy = fmaxf((sy - rmv.y) * (gg.y * rsqrtf(rvv.y + EPS)) + btv.y, 0.f);
    sz = fmaxf((sz - rmv.z) * (gg.z * rsqrtf(rvv.z + EPS)) + btv.z, 0.f);
    sw = fmaxf((sw - rmv.w) * (gg.w * rsqrtf(rvv.w + EPS)) + btv.w, 0.f);

    float4 r = make_float4(sx, sy, sz, sw);
    *(float4*)(out + (size_t)node * 64 + ch) = r;

    if (LAST) {
        int gr = batch[node];
        atomicAdd((float4*)(g_pool + gr * 64 + ch), r);
        if (sub == 0) atomicAdd(&g_gcnt[gr], 1.0f);
    }
}

// ---------------- final output ----------------
__global__ void out_kernel(float* __restrict__ out) {
    int gr = blockIdx.x;
    int c  = threadIdx.x;
    float s  = g_pool[gr * 64 + (c & 63)];
    float cc = fmaxf(g_gcnt[gr], 1.0f);
    out[gr * 128 + c] = (c < 64) ? s / cc : s;
}

// ---------------- launch ----------------
extern "C" void kernel_launch(void* const* d_in, const int* in_sizes, int n_in,
                              void* d_out, int out_size) {
    const float* x     = (const float*)d_in[0];
    const int*   ei    = (const int*)  d_in[1];
    const float* ew    = (const float*)d_in[2];
    const int*   batch = (const int*)  d_in[3];
    const int*   src   = ei;
    const int*   dst   = ei + EE;
    float* out = (float*)d_out;

    const float *Wl[3], *bl[3], *gl[3], *btl[3], *rml[3], *rvl[3];
    for (int l = 0; l < 3; l++) {
        Wl[l]  = (const float*)d_in[4 + 6 * l + 0];
        bl[l]  = (const float*)d_in[4 + 6 * l + 1];
        gl[l]  = (const float*)d_in[4 + 6 * l + 2];
        btl[l] = (const float*)d_in[4 + 6 * l + 3];
        rml[l] = (const float*)d_in[4 + 6 * l + 4];
        rvl[l] = (const float*)d_in[4 + 6 * l + 5];
    }

    float *bufA, *bufB;
    cudaGetSymbolAddress((void**)&bufA, g_bufA);
    cudaGetSymbolAddress((void**)&bufB, g_bufB);

    const int T = 256;
    const int nGrid = (NN + T - 1) / T;
    const int eGrid = (EE + T - 1) / T;

    // ---- CSR build (once; reused by all 3 layers) ----
    init_kernel<<<nGrid, T>>>();
    edge_accum_kernel<<<eGrid, T>>>(dst, ew);
    scan_block_kernel<<<NBLK, 1024>>>();
    scan_bsum_kernel<<<1, 128>>>();
    add_offsets_kernel<<<nGrid, T>>>();
    scatter_kernel<<<eGrid, T>>>(src, dst, ew);

    const int gemmGrid = (NN + 63) / 64;
    const int propGrid = (NN / 2 + 7) / 8;   // 8 warps/block, 2 nodes/warp

    // ---- layer 0 ----
    gemm_kernel<INC><<<gemmGrid, 256>>>(x, Wl[0], bufA);
    prop_fused_kernel<false><<<propGrid, 256>>>(bufA, bl[0], gl[0], btl[0],
                                                rml[0], rvl[0], batch, bufB);
    // ---- layer 1 ----
    gemm_kernel<HC><<<gemmGrid, 256>>>(bufB, Wl[1], bufA);
    prop_fused_kernel<false><<<propGrid, 256>>>(bufA, bl[1], gl[1], btl[1],
                                                rml[1], rvl[1], batch, bufB);
    // ---- layer 2 (fused pooling) ----
    gemm_kernel<HC><<<gemmGrid, 256>>>(bufB, Wl[2], bufA);
    prop_fused_kernel<true><<<propGrid, 256>>>(bufA, bl[2], gl[2], btl[2],
                                               rml[2], rvl[2], batch, bufB);

    out_kernel<<<GG, 128>>>(out);
}

// round 4
// speedup vs baseline: 1.8313x; 1.1419x over previous
#include <cuda_runtime.h>
#include <cuda_fp16.h>
#include <math.h>

#define NN 100000
#define EE 1600000
#define GG 32
#define INC 100
#define HC 64
#define EPS 1e-5f
#define NBLK 98            // ceil(NN/1024)
#define FPS 1048576.0f     // 2^20 fixed-point scale for degree

// ---------------- scratch ----------------
__device__ unsigned long long g_packed[NN];  // (count<<32) | fixedpoint(sum|w|)
__device__ float  g_dinv [NN];
__device__ int    g_cnt_e[NN];
__device__ int    g_rowst[NN];
__device__ int    g_bsum [128];
__device__ int    g_pos  [EE];
__device__ int    g_srcs [EE];
__device__ float  g_wn   [EE];
__device__ __half g_bufH [(size_t)NN * HC];  // fp16 message matrix (GEMM out)
__device__ float  g_bufB [(size_t)NN * HC];  // fp32 layer output (GEMM in)
__device__ float  g_pool [GG * HC];
__device__ float  g_gcnt [GG];

// ---------------- init ----------------
__global__ void init_kernel() {
    int i = blockIdx.x * blockDim.x + threadIdx.x;
    if (i < NN) g_packed[i] = 0ull;
    if (i < GG * HC) g_pool[i] = 0.f;
    if (i < GG) g_gcnt[i] = 0.f;
}

// degree + slot reservation in ONE 64-bit atomic per edge
__global__ void edge_accum_kernel(const int* __restrict__ dst,
                                  const float* __restrict__ ew) {
    int e = blockIdx.x * blockDim.x + threadIdx.x;
    if (e >= EE) return;
    int d = dst[e];
    unsigned int wfix = (unsigned int)(fabsf(ew[e]) * FPS + 0.5f);
    unsigned long long pk = (1ull << 32) | (unsigned long long)wfix;
    unsigned long long old = atomicAdd(&g_packed[d], pk);
    g_pos[e] = (int)(old >> 32);
}

// ---------------- 2-level exclusive scan of counts -> g_rowst ----------------
__global__ void scan_block_kernel() {
    __shared__ int sh[1024];
    int tid = threadIdx.x;
    int i = blockIdx.x * 1024 + tid;
    int v = (i < NN) ? (int)(g_packed[i] >> 32) : 0;
    sh[tid] = v;
    __syncthreads();
    #pragma unroll
    for (int off = 1; off < 1024; off <<= 1) {
        int t = (tid >= off) ? sh[tid - off] : 0;
        __syncthreads();
        sh[tid] += t;
        __syncthreads();
    }
    if (i < NN) g_rowst[i] = sh[tid] - v;
    if (tid == 1023) g_bsum[blockIdx.x] = sh[1023];
}

__global__ void scan_bsum_kernel() {
    __shared__ int sh[128];
    int tid = threadIdx.x;
    int v = (tid < NBLK) ? g_bsum[tid] : 0;
    sh[tid] = v;
    __syncthreads();
    #pragma unroll
    for (int off = 1; off < 128; off <<= 1) {
        int t = (tid >= off) ? sh[tid - off] : 0;
        __syncthreads();
        sh[tid] += t;
        __syncthreads();
    }
    if (tid < NBLK) g_bsum[tid] = sh[tid] - v;
}

__global__ void add_offsets_kernel() {
    int i = blockIdx.x * blockDim.x + threadIdx.x;
    if (i >= NN) return;
    unsigned long long pk = g_packed[i];
    int cnt = (int)(pk >> 32);
    float deg = (float)(unsigned int)(pk & 0xffffffffull) * (1.0f / FPS) + 1.0f;
    g_rowst[i] += g_bsum[i >> 10];
    g_cnt_e[i] = cnt;
    g_dinv[i]  = rsqrtf(deg);
}

// ---------------- scatter edges into CSR (no atomics) ----------------
__global__ void scatter_kernel(const int* __restrict__ src,
                               const int* __restrict__ dst,
                               const float* __restrict__ ew) {
    int e = blockIdx.x * blockDim.x + threadIdx.x;
    if (e >= EE) return;
    int s = src[e], d = dst[e];
    int pos = g_rowst[d] + g_pos[e];
    g_srcs[pos] = s;
    g_wn[pos]   = g_dinv[s] * fabsf(ew[e]) * g_dinv[d];
}

// ---------------- GEMM: Yh[N,64](half) = X[N,DIN](f32) @ W[DIN,64] ----------------
// 128x64 tile, 256 threads, 8x4 micro-tile, K-chunks of 32.
template <int DIN>
__global__ void __launch_bounds__(256) gemm_kernel(const float* __restrict__ X,
                                                   const float* __restrict__ W,
                                                   __half* __restrict__ Yh) {
    __shared__ float Xs[32 * 132];   // [kk][n], n<128, padded
    __shared__ float Ws[32 * 64];    // [kk][c]
    const int t  = threadIdx.x;
    const int tx = t & 15;           // channel quad
    const int ty = t >> 4;           // node octet (0..15)
    const int base = blockIdx.x * 128;

    float4 acc[8];
    #pragma unroll
    for (int r = 0; r < 8; r++) acc[r] = make_float4(0.f, 0.f, 0.f, 0.f);

    for (int k0 = 0; k0 < DIN; k0 += 32) {
        const int kc = (DIN - k0 < 32) ? (DIN - k0) : 32;
        // X tile: 128 nodes x 32 k, transposed into Xs[kk][n]
        #pragma unroll
        for (int it = 0; it < 4; it++) {
            int i  = t + it * 256;         // < 1024
            int n  = i >> 3;
            int kq = (i & 7) << 2;
            float4 v = {0.f, 0.f, 0.f, 0.f};
            int nn = base + n;
            if (nn < NN && kq < kc)
                v = *(const float4*)(X + (size_t)nn * DIN + k0 + kq);
            Xs[(kq + 0) * 132 + n] = v.x;
            Xs[(kq + 1) * 132 + n] = v.y;
            Xs[(kq + 2) * 132 + n] = v.z;
            Xs[(kq + 3) * 132 + n] = v.w;
        }
        // W tile
        #pragma unroll
        for (int it = 0; it < 2; it++) {
            int i  = t + it * 256;         // < 512
            int kk = i >> 4;
            int cq = (i & 15) << 2;
            float4 w = {0.f, 0.f, 0.f, 0.f};
            if (kk < kc)
                w = *(const float4*)(W + (size_t)(k0 + kk) * 64 + cq);
            *(float4*)&Ws[kk * 64 + cq] = w;
        }
        __syncthreads();

        for (int kk = 0; kk < kc; kk++) {
            float4 b  = *(const float4*)&Ws[kk * 64 + (tx << 2)];
            float4 aL = *(const float4*)&Xs[kk * 132 + (ty << 3)];
            float4 aH = *(const float4*)&Xs[kk * 132 + (ty << 3) + 4];
            acc[0].x = fmaf(aL.x, b.x, acc[0].x); acc[0].y = fmaf(aL.x, b.y, acc[0].y);
            acc[0].z = fmaf(aL.x, b.z, acc[0].z); acc[0].w = fmaf(aL.x, b.w, acc[0].w);
            acc[1].x = fmaf(aL.y, b.x, acc[1].x); acc[1].y = fmaf(aL.y, b.y, acc[1].y);
            acc[1].z = fmaf(aL.y, b.z, acc[1].z); acc[1].w = fmaf(aL.y, b.w, acc[1].w);
            acc[2].x = fmaf(aL.z, b.x, acc[2].x); acc[2].y = fmaf(aL.z, b.y, acc[2].y);
            acc[2].z = fmaf(aL.z, b.z, acc[2].z); acc[2].w = fmaf(aL.z, b.w, acc[2].w);
            acc[3].x = fmaf(aL.w, b.x, acc[3].x); acc[3].y = fmaf(aL.w, b.y, acc[3].y);
            acc[3].z = fmaf(aL.w, b.z, acc[3].z); acc[3].w = fmaf(aL.w, b.w, acc[3].w);
            acc[4].x = fmaf(aH.x, b.x, acc[4].x); acc[4].y = fmaf(aH.x, b.y, acc[4].y);
            acc[4].z = fmaf(aH.x, b.z, acc[4].z); acc[4].w = fmaf(aH.x, b.w, acc[4].w);
            acc[5].x = fmaf(aH.y, b.x, acc[5].x); acc[5].y = fmaf(aH.y, b.y, acc[5].y);
            acc[5].z = fmaf(aH.y, b.z, acc[5].z); acc[5].w = fmaf(aH.y, b.w, acc[5].w);
            acc[6].x = fmaf(aH.z, b.x, acc[6].x); acc[6].y = fmaf(aH.z, b.y, acc[6].y);
            acc[6].z = fmaf(aH.z, b.z, acc[6].z); acc[6].w = fmaf(aH.z, b.w, acc[6].w);
            acc[7].x = fmaf(aH.w, b.x, acc[7].x); acc[7].y = fmaf(aH.w, b.y, acc[7].y);
            acc[7].z = fmaf(aH.w, b.z, acc[7].z); acc[7].w = fmaf(aH.w, b.w, acc[7].w);
        }
        __syncthreads();
    }

    const int c0 = tx << 2;
    #pragma unroll
    for (int r = 0; r < 8; r++) {
        int nn = base + (ty << 3) + r;
        if (nn < NN) {
            __half2 lo = __floats2half2_rn(acc[r].x, acc[r].y);
            __half2 hi = __floats2half2_rn(acc[r].z, acc[r].w);
            uint2 u;
            u.x = *(unsigned int*)&lo;
            u.y = *(unsigned int*)&hi;
            *(uint2*)(Yh + (size_t)nn * 64 + c0) = u;
        }
    }
}

// ---------------- fused CSR gather-reduce + BN + ReLU (+ pooling) ----------------
// half-warp (16 lanes) per dst node; lane owns 4 channels (half4 load, fp32 acc)
__device__ __forceinline__ void acc_half4(float4& a, float w, uint2 u) {
    __half2 p0 = *reinterpret_cast<__half2*>(&u.x);
    __half2 p1 = *reinterpret_cast<__half2*>(&u.y);
    float2 f0 = __half22float2(p0);
    float2 f1 = __half22float2(p1);
    a.x = fmaf(w, f0.x, a.x); a.y = fmaf(w, f0.y, a.y);
    a.z = fmaf(w, f1.x, a.z); a.w = fmaf(w, f1.y, a.w);
}

template <bool LAST>
__global__ void prop_fused_kernel(const __half* __restrict__ H,
                                  const float* __restrict__ b,
                                  const float* __restrict__ g,
                                  const float* __restrict__ bt,
                                  const float* __restrict__ rm,
                                  const float* __restrict__ rv,
                                  const int* __restrict__ batch,
                                  float* __restrict__ out) {
    const int warp  = blockIdx.x * (blockDim.x >> 5) + (threadIdx.x >> 5);
    const int lane  = threadIdx.x & 31;
    const int half  = lane >> 4;
    const int sub   = lane & 15;
    const int node  = (warp << 1) + half;
    if (node >= NN) return;
    const int ch = sub << 2;
    const unsigned hmask = half ? 0xffff0000u : 0x0000ffffu;

    const int s0 = g_rowst[node];
    const int s1 = s0 + g_cnt_e[node];

    float4 a0 = {0,0,0,0}, a1 = {0,0,0,0}, a2 = {0,0,0,0}, a3 = {0,0,0,0};

    for (int j = s0; j < s1; j += 16) {
        const int m = min(16, s1 - j);
        int sv = 0; float wv = 0.f;
        if (sub < m) { sv = g_srcs[j + sub]; wv = g_wn[j + sub]; }
        int k = 0;
        for (; k + 4 <= m; k += 4) {
            int   sA = __shfl_sync(hmask, sv, k,     16);
            float wA = __shfl_sync(hmask, wv, k,     16);
            int   sB = __shfl_sync(hmask, sv, k + 1, 16);
            float wB = __shfl_sync(hmask, wv, k + 1, 16);
            int   sC = __shfl_sync(hmask, sv, k + 2, 16);
            float wC = __shfl_sync(hmask, wv, k + 2, 16);
            int   sD = __shfl_sync(hmask, sv, k + 3, 16);
            float wD = __shfl_sync(hmask, wv, k + 3, 16);
            uint2 uA = *(const uint2*)(H + (size_t)sA * 64 + ch);
            uint2 uB = *(const uint2*)(H + (size_t)sB * 64 + ch);
            uint2 uC = *(const uint2*)(H + (size_t)sC * 64 + ch);
            uint2 uD = *(const uint2*)(H + (size_t)sD * 64 + ch);
            acc_half4(a0, wA, uA);
            acc_half4(a1, wB, uB);
            acc_half4(a2, wC, uC);
            acc_half4(a3, wD, uD);
        }
        for (; k < m; k++) {
            int   sA = __shfl_sync(hmask, sv, k, 16);
            float wA = __shfl_sync(hmask, wv, k, 16);
            uint2 uA = *(const uint2*)(H + (size_t)sA * 64 + ch);
            acc_half4(a0, wA, uA);
        }
    }

    // combine + self-loop + bias + BN + ReLU
    const float dv  = g_dinv[node];
    const float dv2 = dv * dv;
    uint2 uh = *(const uint2*)(H + (size_t)node * 64 + ch);
    float4 hv;
    {
        float2 f0 = __half22float2(*reinterpret_cast<__half2*>(&uh.x));
        float2 f1 = __half22float2(*reinterpret_cast<__half2*>(&uh.y));
        hv = make_float4(f0.x, f0.y, f1.x, f1.y);
    }
    float4 bb  = *(const float4*)(b  + ch);
    float4 gg  = *(const float4*)(g  + ch);
    float4 btv = *(const float4*)(bt + ch);
    float4 rmv = *(const float4*)(rm + ch);
    float4 rvv = *(const float4*)(rv + ch);

    float sx = (a0.x + a1.x) + (a2.x + a3.x) + hv.x * dv2 + bb.x;
    float sy = (a0.y + a1.y) + (a2.y + a3.y) + hv.y * dv2 + bb.y;
    float sz = (a0.z + a1.z) + (a2.z + a3.z) + hv.z * dv2 + bb.z;
    float sw = (a0.w + a1.w) + (a2.w + a3.w) + hv.w * dv2 + bb.w;

    sx = fmaxf((sx - rmv.x) * (gg.x * rsqrtf(rvv.x + EPS)) + btv.x, 0.f);
    sy = fmaxf((sy - rmv.y) * (gg.y * rsqrtf(rvv.y + EPS)) + btv.y, 0.f);
    sz = fmaxf((sz - rmv.z) * (gg.z * rsqrtf(rvv.z + EPS)) + btv.z, 0.f);
    sw = fmaxf((sw - rmv.w) * (gg.w * rsqrtf(rvv.w + EPS)) + btv.w, 0.f);

    float4 r = make_float4(sx, sy, sz, sw);
    *(float4*)(out + (size_t)node * 64 + ch) = r;

    if (LAST) {
        int gr = batch[node];
        atomicAdd((float4*)(g_pool + gr * 64 + ch), r);
        if (sub == 0) atomicAdd(&g_gcnt[gr], 1.0f);
    }
}

// ---------------- final output ----------------
__global__ void out_kernel(float* __restrict__ out) {
    int gr = blockIdx.x;
    int c  = threadIdx.x;
    float s  = g_pool[gr * 64 + (c & 63)];
    float cc = fmaxf(g_gcnt[gr], 1.0f);
    out[gr * 128 + c] = (c < 64) ? s / cc : s;
}

// ---------------- launch ----------------
extern "C" void kernel_launch(void* const* d_in, const int* in_sizes, int n_in,
                              void* d_out, int out_size) {
    const float* x     = (const float*)d_in[0];
    const int*   ei    = (const int*)  d_in[1];
    const float* ew    = (const float*)d_in[2];
    const int*   batch = (const int*)  d_in[3];
    const int*   src   = ei;
    const int*   dst   = ei + EE;
    float* out = (float*)d_out;

    const float *Wl[3], *bl[3], *gl[3], *btl[3], *rml[3], *rvl[3];
    for (int l = 0; l < 3; l++) {
        Wl[l]  = (const float*)d_in[4 + 6 * l + 0];
        bl[l]  = (const float*)d_in[4 + 6 * l + 1];
        gl[l]  = (const float*)d_in[4 + 6 * l + 2];
        btl[l] = (const float*)d_in[4 + 6 * l + 3];
        rml[l] = (const float*)d_in[4 + 6 * l + 4];
        rvl[l] = (const float*)d_in[4 + 6 * l + 5];
    }

    __half* bufH; float* bufB;
    cudaGetSymbolAddress((void**)&bufH, g_bufH);
    cudaGetSymbolAddress((void**)&bufB, g_bufB);

    const int T = 256;
    const int nGrid = (NN + T - 1) / T;
    const int eGrid = (EE + T - 1) / T;

    // ---- CSR build (once; reused by all 3 layers) ----
    init_kernel<<<nGrid, T>>>();
    edge_accum_kernel<<<eGrid, T>>>(dst, ew);
    scan_block_kernel<<<NBLK, 1024>>>();
    scan_bsum_kernel<<<1, 128>>>();
    add_offsets_kernel<<<nGrid, T>>>();
    scatter_kernel<<<eGrid, T>>>(src, dst, ew);

    const int gemmGrid = (NN + 127) / 128;
    const int propGrid = (NN / 2 + 7) / 8;   // 8 warps/block, 2 nodes/warp

    // ---- layer 0 ----
    gemm_kernel<INC><<<gemmGrid, 256>>>(x, Wl[0], bufH);
    prop_fused_kernel<false><<<propGrid, 256>>>(bufH, bl[0], gl[0], btl[0],
                                                rml[0], rvl[0], batch, bufB);
    // ---- layer 1 ----
    gemm_kernel<HC><<<gemmGrid, 256>>>(bufB, Wl[1], bufH);
    prop_fused_kernel<false><<<propGrid, 256>>>(bufH, bl[1], gl[1], btl[1],
                                                rml[1], rvl[1], batch, bufB);
    // ---- layer 2 (fused pooling) ----
    gemm_kernel<HC><<<gemmGrid, 256>>>(bufB, Wl[2], bufH);
    prop_fused_kernel<true><<<propGrid, 256>>>(bufH, bl[2], gl[2], btl[2],
                                               rml[2], rvl[2], batch, bufB);

    out_kernel<<<GG, 128>>>(out);
}